// round 1
// baseline (speedup 1.0000x reference)
#include <cuda_runtime.h>

// iwt db1 inverse: x (16,128,128,128) f32, filters (2,2,2) f32 -> out (16,64,256,256) f32
// out[bg, 2h+i, 2w+j] = x[2bg, h, w]*f0[i][j] + x[2bg+1, h, w]*f1[i][j]
//
// Pure bandwidth problem: 128 MiB in + 256 MiB out. Each thread: 4 input pixels
// per channel pair (2x float4 loads), 4x float4 stores (two per output row).

static constexpr int H  = 128;
static constexpr int W  = 128;
static constexpr int HW = H * W;           // 16384
static constexpr int WQ = W / 4;           // 32 quads per input row
static constexpr int OW = 2 * W;           // 256 output row width
static constexpr int NBG = 16 * 64;        // batch*group = 1024
static constexpr long long NTHREADS = (long long)NBG * H * WQ;  // 4,194,304

__global__ __launch_bounds__(256) void iwt_kernel(
    const float* __restrict__ x,
    const float* __restrict__ filt,
    float* __restrict__ out)
{
    int tid = blockIdx.x * blockDim.x + threadIdx.x;

    int wq = tid & (WQ - 1);          // 0..31
    int h  = (tid / WQ) & (H - 1);    // 0..127
    int bg = tid / (WQ * H);          // 0..1023  (b*64 + g)

    // filters: filt[0..3] = f0[i][j], filt[4..7] = f1[i][j]  (i*2+j)
    float f000 = __ldg(filt + 0), f001 = __ldg(filt + 1);
    float f010 = __ldg(filt + 2), f011 = __ldg(filt + 3);
    float f100 = __ldg(filt + 4), f101 = __ldg(filt + 5);
    float f110 = __ldg(filt + 6), f111 = __ldg(filt + 7);

    // input: channel c0 = 2*bg, c1 = 2*bg+1
    long long in_off = ((long long)(2 * bg) * H + h) * W + 4 * wq;
    float4 a = *reinterpret_cast<const float4*>(x + in_off);        // x0, 4 pixels
    float4 b = *reinterpret_cast<const float4*>(x + in_off + HW);   // x1, 4 pixels

    // output rows 2h and 2h+1, columns starting at 8*wq
    long long out_off = ((long long)bg * (2 * H) + 2 * h) * OW + 8 * wq;

    // top row (i=0): per pixel p -> [p*f000+q*f100, p*f001+q*f101]
    float4 t0, t1, b0, b1;
    t0.x = a.x * f000 + b.x * f100;  t0.y = a.x * f001 + b.x * f101;
    t0.z = a.y * f000 + b.y * f100;  t0.w = a.y * f001 + b.y * f101;
    t1.x = a.z * f000 + b.z * f100;  t1.y = a.z * f001 + b.z * f101;
    t1.z = a.w * f000 + b.w * f100;  t1.w = a.w * f001 + b.w * f101;
    // bottom row (i=1)
    b0.x = a.x * f010 + b.x * f110;  b0.y = a.x * f011 + b.x * f111;
    b0.z = a.y * f010 + b.y * f110;  b0.w = a.y * f011 + b.y * f111;
    b1.x = a.z * f010 + b.z * f110;  b1.y = a.z * f011 + b.z * f111;
    b1.z = a.w * f010 + b.w * f110;  b1.w = a.w * f011 + b.w * f111;

    *reinterpret_cast<float4*>(out + out_off)          = t0;
    *reinterpret_cast<float4*>(out + out_off + 4)      = t1;
    *reinterpret_cast<float4*>(out + out_off + OW)     = b0;
    *reinterpret_cast<float4*>(out + out_off + OW + 4) = b1;
}

extern "C" void kernel_launch(void* const* d_in, const int* in_sizes, int n_in,
                              void* d_out, int out_size)
{
    const float* x    = (const float*)d_in[0];
    const float* filt = (const float*)d_in[1];
    float* out        = (float*)d_out;

    int threads = 256;
    int blocks  = (int)(NTHREADS / threads);   // 16384
    iwt_kernel<<<blocks, threads>>>(x, filt, out);
}

// round 3
// speedup vs baseline: 1.0723x; 1.0723x over previous
#include <cuda_runtime.h>

// iwt db1 inverse: x (16,128,128,128) f32, filters (2,2,2) f32 -> out (16,64,256,256) f32
// out[bg, 2h+i, 2w+j] = x[2bg, h, w]*f0[i][j] + x[2bg+1, h, w]*f1[i][j]
//
// Bandwidth problem (128 MiB in + 256 MiB out). Key layout rule: every
// load/store instruction must be DENSE across the warp (R1 showed L1tex
// wavefront throttling from 32B-strided 16B stores).
//
// Mapping: one "work item" = one input pixel PAIR (2 adjacent w-pixels) for
// one channel pair. Per item: 2x float2 loads (8B, lane-stride 8B -> 256B
// dense/warp) and 2x float4 stores (16B, lane-stride 16B -> 512B dense/warp),
// one per output row. Each thread does 2 items from disjoint tensor halves
// for MLP=4 front-batched loads.

static constexpr int H  = 128;
static constexpr int W  = 128;
static constexpr int HW = H * W;            // 16384
static constexpr int WP = W / 2;            // 64 pixel-pairs per input row
static constexpr int OW = 2 * W;            // 256 output row width
static constexpr int NBG = 16 * 64;         // 1024
static constexpr long long NPAIRS = (long long)NBG * H * WP;   // 8,388,608
static constexpr long long HALF   = NPAIRS / 2;                // 4,194,304

struct Filt {
    float f000, f001, f010, f011, f100, f101, f110, f111;
};

__device__ __forceinline__ void decode(long long t, long long& in_off, long long& out_off)
{
    int p  = (int)(t & (WP - 1));        // pair index in row
    int h  = (int)((t >> 6) & (H - 1));  // input row
    int bg = (int)(t >> 13);             // b*64 + g
    in_off  = ((long long)(2 * bg) * H + h) * W + 2 * p;
    out_off = ((long long)bg * (2 * H) + 2 * h) * OW + 4 * p;
}

__device__ __forceinline__ void emit(const float2 a, const float2 b, const Filt f,
                                     float* __restrict__ out, long long out_off)
{
    float4 t, btm;
    t.x   = a.x * f.f000 + b.x * f.f100;  t.y   = a.x * f.f001 + b.x * f.f101;
    t.z   = a.y * f.f000 + b.y * f.f100;  t.w   = a.y * f.f001 + b.y * f.f101;
    btm.x = a.x * f.f010 + b.x * f.f110;  btm.y = a.x * f.f011 + b.x * f.f111;
    btm.z = a.y * f.f010 + b.y * f.f110;  btm.w = a.y * f.f011 + b.y * f.f111;
    __stcs(reinterpret_cast<float4*>(out + out_off),      t);
    __stcs(reinterpret_cast<float4*>(out + out_off + OW), btm);
}

__global__ __launch_bounds__(256) void iwt_kernel(
    const float* __restrict__ x,
    const float* __restrict__ filt,
    float* __restrict__ out)
{
    long long tid = (long long)blockIdx.x * blockDim.x + threadIdx.x;

    Filt f;
    f.f000 = __ldg(filt + 0); f.f001 = __ldg(filt + 1);
    f.f010 = __ldg(filt + 2); f.f011 = __ldg(filt + 3);
    f.f100 = __ldg(filt + 4); f.f101 = __ldg(filt + 5);
    f.f110 = __ldg(filt + 6); f.f111 = __ldg(filt + 7);

    long long in0, out0, in1, out1;
    decode(tid,        in0, out0);
    decode(tid + HALF, in1, out1);

    // Front-batched loads: 4 independent LDG.64, all dense across the warp.
    float2 a0 = __ldcs(reinterpret_cast<const float2*>(x + in0));
    float2 b0 = __ldcs(reinterpret_cast<const float2*>(x + in0 + HW));
    float2 a1 = __ldcs(reinterpret_cast<const float2*>(x + in1));
    float2 b1 = __ldcs(reinterpret_cast<const float2*>(x + in1 + HW));

    emit(a0, b0, f, out, out0);
    emit(a1, b1, f, out, out1);
}

extern "C" void kernel_launch(void* const* d_in, const int* in_sizes, int n_in,
                              void* d_out, int out_size)
{
    const float* x    = (const float*)d_in[0];
    const float* filt = (const float*)d_in[1];
    float* out        = (float*)d_out;

    int threads = 256;
    int blocks  = (int)(HALF / threads);   // 16384
    iwt_kernel<<<blocks, threads>>>(x, filt, out);
}